// round 11
// baseline (speedup 1.0000x reference)
#include <cuda_runtime.h>

#define B_  4
#define N_  16384
#define M_  4096
#define K_  16
#define R2  0.25f
#define NQ  (B_ * M_)
#define NPAIR (N_ / 2)            // 8192 pair-slots per batch
#define LONG_THRESH 4.0f   // |q|^2 above this => long scan, schedule first

// Scratch (device globals; no allocation allowed)
__device__ float4       g_pts[B_ * N_];          // (x,y,z,|p|^2) AoS (MLP gather)
__device__ ulonglong2   g_pA[B_ * NPAIR];        // {x_i,x_j, y_i,y_j} packed pairs
__device__ ulonglong2   g_pB[B_ * NPAIR];        // {z_i,z_j, w_i,w_j} packed pairs
__device__ unsigned int g_qctr;                  // work-stealing queue head
__device__ unsigned int g_front;                 // long-query segment fill
__device__ unsigned int g_back;                  // short-query segment fill
__device__ int          g_order[NQ];

// ---- packed f32x2 helpers (per-element IEEE rn, identical to scalar rn) ----
__device__ __forceinline__ unsigned long long pk2(float lo, float hi) {
    unsigned long long r;
    asm("mov.b64 %0, {%1, %2};" : "=l"(r) : "f"(lo), "f"(hi));
    return r;
}
__device__ __forceinline__ void unpk2(unsigned long long v, float& lo, float& hi) {
    asm("mov.b64 {%0, %1}, %2;" : "=f"(lo), "=f"(hi) : "l"(v));
}
__device__ __forceinline__ unsigned long long pmul(unsigned long long a, unsigned long long b) {
    unsigned long long r;
    asm("mul.rn.f32x2 %0, %1, %2;" : "=l"(r) : "l"(a), "l"(b));
    return r;
}
__device__ __forceinline__ unsigned long long padd(unsigned long long a, unsigned long long b) {
    unsigned long long r;
    asm("add.rn.f32x2 %0, %1, %2;" : "=l"(r) : "l"(a), "l"(b));
    return r;
}

// prep: one thread per pair (i, i+32) within a 64-point chunk.
// Writes AoS g_pts for both points AND the packed pair arrays.
__global__ __launch_bounds__(256) void prep_kernel(const float* __restrict__ xyz) {
    int t = blockIdx.x * blockDim.x + threadIdx.x;      // 0 .. B_*NPAIR-1
    if (t == 0) { g_qctr = 0; g_front = 0; g_back = 0; }
    if (t >= B_ * NPAIR) return;
    int b  = t >> 13;               // / NPAIR (8192)
    int s  = t & (NPAIR - 1);
    int c  = s >> 5;                // 64-pt chunk
    int l  = s & 31;
    int il = c * 64 + l;            // first point of pair
    int jl = il + 32;               // second point of pair
    int gi = b * N_ + il;
    int gj = b * N_ + jl;

    float xi = xyz[3 * gi + 0], yi = xyz[3 * gi + 1], zi = xyz[3 * gi + 2];
    float xj = xyz[3 * gj + 0], yj = xyz[3 * gj + 1], zj = xyz[3 * gj + 2];
    // match jnp.sum(x**2,-1): (x*x + y*y) + z*z, no fma contraction
    float wi = __fadd_rn(__fadd_rn(__fmul_rn(xi, xi), __fmul_rn(yi, yi)), __fmul_rn(zi, zi));
    float wj = __fadd_rn(__fadd_rn(__fmul_rn(xj, xj), __fmul_rn(yj, yj)), __fmul_rn(zj, zj));

    g_pts[gi] = make_float4(xi, yi, zi, wi);
    g_pts[gj] = make_float4(xj, yj, zj, wj);
    g_pA[t]   = make_ulonglong2(pk2(xi, xj), pk2(yi, yj));
    g_pB[t]   = make_ulonglong2(pk2(zi, zj), pk2(wi, wj));
}

// LPT scheduling: long-scan queries (large |q|^2) go to the front of the
// queue, short ones to the back. Processing order doesn't affect results.
__global__ __launch_bounds__(256) void order_kernel(const int* __restrict__ fps_idx) {
    int qid = blockIdx.x * blockDim.x + threadIdx.x;
    if (qid >= NQ) return;
    int b = qid >> 12;
    float w = g_pts[(size_t)b * N_ + fps_idx[qid]].w;
    int pos;
    if (w > LONG_THRESH) pos = (int)atomicAdd(&g_front, 1u);
    else                 pos = NQ - 1 - (int)atomicAdd(&g_back, 1u);
    g_order[pos] = qid;
}

// packed d2 for a point pair. Algebra: (q.w+p.w) + (-2)*dot == (q.w+p.w) - 2*dot
// exactly in IEEE rn (sign flip is exact; a+(-b) == a-b). Per-element rounding
// identical to the scalar __fmul_rn/__fadd_rn reference chain.
__device__ __forceinline__ unsigned long long d2pair(
    ulonglong2 a, ulonglong2 bb,
    unsigned long long qx2, unsigned long long qy2,
    unsigned long long qz2, unsigned long long qw2,
    unsigned long long nm2)
{
    unsigned long long dot = padd(padd(pmul(qx2, a.x), pmul(qy2, a.y)), pmul(qz2, bb.x));
    return padd(padd(qw2, bb.y), pmul(nm2, dot));
}

// take up to (K_ - found) lowest set bits of mask, in ascending order;
// lane r (r = lane - found) claims the (r+1)-th set bit. Warp-parallel.
__device__ __forceinline__ void extract_fns(unsigned mask, int base, int lane,
                                            int& found, int& my_idx) {
    int c = __popc(mask);
    if (c) {
        int take = K_ - found;
        if (take > c) take = c;
        int r = lane - found;
        if (r >= 0 && r < take) {
            my_idx = base + __fns(mask, 0, r + 1);
        }
        found += take;
    }
}

__global__ __launch_bounds__(256, 4) void sa_kernel(
    const float* __restrict__ feat,
    const int*   __restrict__ fps_idx,
    const float* __restrict__ W1,
    const float* __restrict__ b1,
    const float* __restrict__ W2,
    const float* __restrict__ b2,
    float*       __restrict__ out)
{
    const unsigned FULL = 0xffffffffu;
    int lane = threadIdx.x & 31;

    // hoist this lane's weight columns into registers (inner loops become
    // pure SHFL+FFMA, no LDS/LDG)
    float w1r[6], w2r[32];
    #pragma unroll
    for (int i = 0; i < 6; i++)  w1r[i] = W1[i * 32 + lane];
    #pragma unroll
    for (int i = 0; i < 32; i++) w2r[i] = W2[i * 32 + lane];
    float b1r = b1[lane];
    float b2r = b2[lane];

    const unsigned long long nm2 = pk2(-2.0f, -2.0f);

    // persistent warp: steal one query at a time, longest-first order
    for (;;) {
        int idx;
        if (lane == 0) idx = (int)atomicAdd(&g_qctr, 1u);
        idx = __shfl_sync(FULL, idx, 0);
        if (idx >= NQ) break;
        int qid = g_order[idx];

        int b = qid >> 12;            // / M_ (4096)
        const float4*     __restrict__ pts = g_pts + (size_t)b * N_;
        const ulonglong2* __restrict__ pA  = g_pA + (size_t)b * NPAIR + lane;
        const ulonglong2* __restrict__ pB  = g_pB + (size_t)b * NPAIR + lane;

        float4 q = pts[fps_idx[qid]];
        unsigned long long qx2 = pk2(q.x, q.x);
        unsigned long long qy2 = pk2(q.y, q.y);
        unsigned long long qz2 = pk2(q.z, q.z);
        unsigned long long qw2 = pk2(q.w, q.w);

        // ---- ball query: first K_ in-ball indices in ascending order ----
        // 8 independent 16B loads = 4 pair-groups = 256 points per iteration;
        // 2 points per lane evaluated with packed f32x2 math.
        int found  = 0;
        int my_idx = 0;               // lane k (k<K_) owns neighbor k
        for (int base = 0; base < N_; base += 256, pA += 128, pB += 128) {
            ulonglong2 a0 = pA[0],  b0 = pB[0];
            ulonglong2 a1 = pA[32], b1v = pB[32];
            ulonglong2 a2 = pA[64], b2v = pB[64];
            ulonglong2 a3 = pA[96], b3v = pB[96];

            unsigned long long d0 = d2pair(a0, b0,  qx2, qy2, qz2, qw2, nm2);
            unsigned long long d1 = d2pair(a1, b1v, qx2, qy2, qz2, qw2, nm2);
            unsigned long long d2v = d2pair(a2, b2v, qx2, qy2, qz2, qw2, nm2);
            unsigned long long d3 = d2pair(a3, b3v, qx2, qy2, qz2, qw2, nm2);

            float l0, h0, l1, h1, l2, h2, l3, h3;
            unpk2(d0, l0, h0);
            unpk2(d1, l1, h1);
            unpk2(d2v, l2, h2);
            unpk2(d3, l3, h3);

            // lo half = points [base+g*64, +32), hi half = [base+g*64+32, +64)
            unsigned m0 = __ballot_sync(FULL, l0 <= R2);
            unsigned m1 = __ballot_sync(FULL, h0 <= R2);
            unsigned m2 = __ballot_sync(FULL, l1 <= R2);
            unsigned m3 = __ballot_sync(FULL, h1 <= R2);
            unsigned m4 = __ballot_sync(FULL, l2 <= R2);
            unsigned m5 = __ballot_sync(FULL, h2 <= R2);
            unsigned m6 = __ballot_sync(FULL, l3 <= R2);
            unsigned m7 = __ballot_sync(FULL, h3 <= R2);
            unsigned any = (m0 | m1) | (m2 | m3) | ((m4 | m5) | (m6 | m7));
            if (any) {
                extract_fns(m0, base,       lane, found, my_idx);
                extract_fns(m1, base +  32, lane, found, my_idx);
                extract_fns(m2, base +  64, lane, found, my_idx);
                extract_fns(m3, base +  96, lane, found, my_idx);
                extract_fns(m4, base + 128, lane, found, my_idx);
                extract_fns(m5, base + 160, lane, found, my_idx);
                extract_fns(m6, base + 192, lane, found, my_idx);
                extract_fns(m7, base + 224, lane, found, my_idx);
                if (found >= K_) break;
            }
        }
        // pad missing neighbors with the first valid one (reference
        // semantics); found >= 1 always (query is in its own ball).
        int idx0 = __shfl_sync(FULL, my_idx, 0);
        if (lane >= found) my_idx = idx0;
        int kmax = found < K_ ? found : K_;   // padded dups can't change max

        // ---- MLP + maxpool: lane j owns output channel j ----
        const float* __restrict__ featb = feat + (size_t)b * N_ * 3;
        float acc = -3.402823466e38f;

        #pragma unroll 1
        for (int k = 0; k < kmax; k++) {
            int g = __shfl_sync(FULL, my_idx, k);
            float4 p = pts[g];                    // broadcast load (L1/L2 hit)
            float f0 = featb[3 * g + 0];
            float f1 = featb[3 * g + 1];
            float f2 = featb[3 * g + 2];
            float i0 = p.x - q.x, i1 = p.y - q.y, i2 = p.z - q.z;

            float h1 = b1r;
            h1 += i0 * w1r[0];
            h1 += i1 * w1r[1];
            h1 += i2 * w1r[2];
            h1 += f0 * w1r[3];
            h1 += f1 * w1r[4];
            h1 += f2 * w1r[5];
            h1 = fmaxf(h1, 0.1f * h1);            // leaky relu

            // 4 accumulator chains to break the serial FMA dependency
            float a0 = b2r, a1 = 0.f, a2 = 0.f, a3 = 0.f;
            #pragma unroll
            for (int i = 0; i < 32; i += 4) {
                a0 = fmaf(__shfl_sync(FULL, h1, i + 0), w2r[i + 0], a0);
                a1 = fmaf(__shfl_sync(FULL, h1, i + 1), w2r[i + 1], a1);
                a2 = fmaf(__shfl_sync(FULL, h1, i + 2), w2r[i + 2], a2);
                a3 = fmaf(__shfl_sync(FULL, h1, i + 3), w2r[i + 3], a3);
            }
            float h2 = (a0 + a1) + (a2 + a3);
            h2 = fmaxf(h2, 0.1f * h2);

            acc = fmaxf(acc, h2);
        }

        out[((size_t)qid) * 32 + lane] = acc;
    }
}

extern "C" void kernel_launch(void* const* d_in, const int* in_sizes, int n_in,
                              void* d_out, int out_size) {
    const float* xyz     = (const float*)d_in[0];
    const float* feat    = (const float*)d_in[1];
    const int*   fps_idx = (const int*)  d_in[2];
    const float* W1      = (const float*)d_in[3];
    const float* b1      = (const float*)d_in[4];
    const float* W2      = (const float*)d_in[5];
    const float* b2      = (const float*)d_in[6];
    float* out = (float*)d_out;

    prep_kernel<<<(B_ * NPAIR + 255) / 256, 256>>>(xyz);
    order_kernel<<<NQ / 256, 256>>>(fps_idx);
    // persistent kernel: 4 CTAs/SM, work-stealing queue, longest-first
    sa_kernel<<<592, 256>>>(feat, fps_idx, W1, b1, W2, b2, out);
    (void)in_sizes; (void)n_in; (void)out_size;
}

// round 13
// speedup vs baseline: 1.1438x; 1.1438x over previous
#include <cuda_runtime.h>

#define B_  4
#define N_  16384
#define M_  4096
#define K_  16
#define R2  0.25f
#define NQ  (B_ * M_)
#define LONG_THRESH 4.0f   // |q|^2 above this => long scan, schedule first

// Scratch (device globals; no allocation allowed)
__device__ float4       g_pts[B_ * N_];   // (x, y, z, |p|^2)  -- MLP + query load
__device__ float4       g_n2p[B_ * N_];   // (-2x, -2y, -2z, |p|^2) -- scan array
__device__ unsigned int g_qctr;           // work-stealing queue head
__device__ unsigned int g_front;          // long-query segment fill
__device__ unsigned int g_back;           // short-query segment fill
__device__ int          g_order[NQ];

__global__ __launch_bounds__(256) void prep_kernel(const float* __restrict__ xyz) {
    int i = blockIdx.x * blockDim.x + threadIdx.x;
    if (i == 0) { g_qctr = 0; g_front = 0; g_back = 0; }   // graph-replay safe
    if (i < B_ * N_) {
        float x = xyz[3 * i + 0];
        float y = xyz[3 * i + 1];
        float z = xyz[3 * i + 2];
        // match jnp.sum(x**2,-1): (x*x + y*y) + z*z, no fma contraction
        float sq = __fadd_rn(__fadd_rn(__fmul_rn(x, x), __fmul_rn(y, y)), __fmul_rn(z, z));
        g_pts[i] = make_float4(x, y, z, sq);
        // -2*coord is exact (power-of-2 scale + sign flip); lets the scan form
        // rn(rn(qw+pw) + dotn), bit-identical to rn(rn(qw+pw) - rn(2*dot)).
        g_n2p[i] = make_float4(-2.0f * x, -2.0f * y, -2.0f * z, sq);
    }
}

// LPT scheduling: long-scan queries (large |q|^2) go to the front of the
// queue, short ones to the back. Processing order doesn't affect results.
__global__ __launch_bounds__(256) void order_kernel(const int* __restrict__ fps_idx) {
    int qid = blockIdx.x * blockDim.x + threadIdx.x;
    if (qid >= NQ) return;
    int b = qid >> 12;
    float w = g_pts[(size_t)b * N_ + fps_idx[qid]].w;
    int pos;
    if (w > LONG_THRESH) pos = (int)atomicAdd(&g_front, 1u);
    else                 pos = NQ - 1 - (int)atomicAdd(&g_back, 1u);
    g_order[pos] = qid;
}

// d2 with pre-scaled point: dotn = ((qx*nx + qy*ny) + qz*nz) where n = -2p.
// Each partial is exactly -2x the reference partial, so the final
// rn(rn(qw+pw) + dotn) == rn(rn(qw+pw) - rn(2*dot_ref)) bit-for-bit.
__device__ __forceinline__ float d2n(float4 q, float4 n) {
    float dotn = __fadd_rn(__fadd_rn(__fmul_rn(q.x, n.x), __fmul_rn(q.y, n.y)),
                           __fmul_rn(q.z, n.z));
    return __fadd_rn(__fadd_rn(q.w, n.w), dotn);
}

__global__ __launch_bounds__(256, 4) void sa_kernel(
    const float* __restrict__ feat,
    const int*   __restrict__ fps_idx,
    const float* __restrict__ W1,
    const float* __restrict__ b1,
    const float* __restrict__ W2,
    const float* __restrict__ b2,
    float*       __restrict__ out)
{
    const unsigned FULL = 0xffffffffu;
    int lane = threadIdx.x & 31;

    // hoist this lane's weight columns into registers (inner loops become
    // pure SHFL+FFMA, no LDS/LDG)
    float w1r[6], w2r[32];
    #pragma unroll
    for (int i = 0; i < 6; i++)  w1r[i] = W1[i * 32 + lane];
    #pragma unroll
    for (int i = 0; i < 32; i++) w2r[i] = W2[i * 32 + lane];
    float b1r = b1[lane];
    float b2r = b2[lane];

    // persistent warp: steal one query at a time, longest-first order
    for (;;) {
        int idx;
        if (lane == 0) idx = (int)atomicAdd(&g_qctr, 1u);
        idx = __shfl_sync(FULL, idx, 0);
        if (idx >= NQ) break;
        int qid = g_order[idx];

        int b = qid >> 12;            // / M_ (4096)
        const float4* __restrict__ pts = g_pts + (size_t)b * N_;
        const float4* __restrict__ pl  = g_n2p + (size_t)b * N_ + lane;

        float4 q = pts[fps_idx[qid]];

        // ---- ball query: first K_ in-ball indices in ascending order ----
        // 8 independent 16B loads (256 points) in flight before the exit check.
        int found  = 0;
        int my_idx = 0;               // lane k (k<K_) owns neighbor k
        for (int base = 0; base < N_; base += 256, pl += 256) {
            float4 p0 = pl[0];
            float4 p1 = pl[32];
            float4 p2 = pl[64];
            float4 p3 = pl[96];
            float4 p4 = pl[128];
            float4 p5 = pl[160];
            float4 p6 = pl[192];
            float4 p7 = pl[224];
            unsigned m0 = __ballot_sync(FULL, d2n(q, p0) <= R2);
            unsigned m1 = __ballot_sync(FULL, d2n(q, p1) <= R2);
            unsigned m2 = __ballot_sync(FULL, d2n(q, p2) <= R2);
            unsigned m3 = __ballot_sync(FULL, d2n(q, p3) <= R2);
            unsigned m4 = __ballot_sync(FULL, d2n(q, p4) <= R2);
            unsigned m5 = __ballot_sync(FULL, d2n(q, p5) <= R2);
            unsigned m6 = __ballot_sync(FULL, d2n(q, p6) <= R2);
            unsigned m7 = __ballot_sync(FULL, d2n(q, p7) <= R2);
            unsigned any = (m0 | m1) | (m2 | m3) | ((m4 | m5) | (m6 | m7));
            if (any) {
                // parallel rank-select: lane k (found <= k < found+T) takes the
                // (k-found)-th set bit across m0..m7 in ascending group/bit
                // order -- identical selection to a serial per-mask walk.
                int s0 = __popc(m0);
                int s1 = s0 + __popc(m1);
                int s2 = s1 + __popc(m2);
                int s3 = s2 + __popc(m3);
                int s4 = s3 + __popc(m4);
                int s5 = s4 + __popc(m5);
                int s6 = s5 + __popc(m6);
                int T  = s6 + __popc(m7);
                int r  = lane - found;     // rank this lane seeks in the chunk
                if (r >= 0 && r < T && lane < K_) {
                    unsigned mm; int e, off;
                    if (r < s3) {
                        if (r < s1) {
                            if (r < s0) { mm = m0; e = 0;  off = 0;  }
                            else        { mm = m1; e = s0; off = 32; }
                        } else {
                            if (r < s2) { mm = m2; e = s1; off = 64; }
                            else        { mm = m3; e = s2; off = 96; }
                        }
                    } else {
                        if (r < s5) {
                            if (r < s4) { mm = m4; e = s3; off = 128; }
                            else        { mm = m5; e = s4; off = 160; }
                        } else {
                            if (r < s6) { mm = m6; e = s5; off = 192; }
                            else        { mm = m7; e = s6; off = 224; }
                        }
                    }
                    my_idx = base + off + __fns(mm, 0, (r - e) + 1);
                }
                found += T;
                if (found >= K_) { found = K_; break; }
            }
        }
        // pad missing neighbors with the first valid one (reference
        // semantics); found >= 1 always (query is in its own ball).
        int idx0 = __shfl_sync(FULL, my_idx, 0);
        if (lane >= found) my_idx = idx0;
        int kmax = found;                     // padded dups can't change max

        // ---- MLP + maxpool: lane j owns output channel j ----
        const float* __restrict__ featb = feat + (size_t)b * N_ * 3;
        float acc = -3.402823466e38f;

        #pragma unroll 1
        for (int k = 0; k < kmax; k++) {
            int g = __shfl_sync(FULL, my_idx, k);
            float4 p = pts[g];                    // broadcast load (L1/L2 hit)
            float f0 = featb[3 * g + 0];
            float f1 = featb[3 * g + 1];
            float f2 = featb[3 * g + 2];
            float i0 = p.x - q.x, i1 = p.y - q.y, i2 = p.z - q.z;

            float h1 = b1r;
            h1 += i0 * w1r[0];
            h1 += i1 * w1r[1];
            h1 += i2 * w1r[2];
            h1 += f0 * w1r[3];
            h1 += f1 * w1r[4];
            h1 += f2 * w1r[5];
            h1 = fmaxf(h1, 0.1f * h1);            // leaky relu

            // 4 accumulator chains to break the serial FMA dependency
            float a0 = b2r, a1 = 0.f, a2 = 0.f, a3 = 0.f;
            #pragma unroll
            for (int i = 0; i < 32; i += 4) {
                a0 = fmaf(__shfl_sync(FULL, h1, i + 0), w2r[i + 0], a0);
                a1 = fmaf(__shfl_sync(FULL, h1, i + 1), w2r[i + 1], a1);
                a2 = fmaf(__shfl_sync(FULL, h1, i + 2), w2r[i + 2], a2);
                a3 = fmaf(__shfl_sync(FULL, h1, i + 3), w2r[i + 3], a3);
            }
            float h2 = (a0 + a1) + (a2 + a3);
            h2 = fmaxf(h2, 0.1f * h2);

            acc = fmaxf(acc, h2);
        }

        out[((size_t)qid) * 32 + lane] = acc;
    }
}

extern "C" void kernel_launch(void* const* d_in, const int* in_sizes, int n_in,
                              void* d_out, int out_size) {
    const float* xyz     = (const float*)d_in[0];
    const float* feat    = (const float*)d_in[1];
    const int*   fps_idx = (const int*)  d_in[2];
    const float* W1      = (const float*)d_in[3];
    const float* b1      = (const float*)d_in[4];
    const float* W2      = (const float*)d_in[5];
    const float* b2      = (const float*)d_in[6];
    float* out = (float*)d_out;

    prep_kernel<<<(B_ * N_ + 255) / 256, 256>>>(xyz);
    order_kernel<<<NQ / 256, 256>>>(fps_idx);
    // persistent kernel: 4 CTAs/SM, work-stealing queue, longest-first
    sa_kernel<<<592, 256>>>(feat, fps_idx, W1, b1, W2, b2, out);
    (void)in_sizes; (void)n_in; (void)out_size;
}